// round 1
// baseline (speedup 1.0000x reference)
#include <cuda_runtime.h>
#include <math.h>

#define Bb 128
#define Ss 1024
#define Dd 512
#define Nn 784

// ---------------- scratch (no allocations allowed) ----------------
__device__ float g_u[2 * Dd];        // Wa @ Wc  : [2D]
__device__ float g_w[Bb * Dd];       // fused logit weights per (b,d)
__device__ float g_pooled[Bb * Dd];  // attention-pooled features

// ---------------- kernel 1: u = Wa @ Wc ----------------
// Wa: [1, D], Wc: [D, 2D] row-major. u[j] = sum_d Wa[d] * Wc[d*2D + j]
__global__ void u_kernel(const float* __restrict__ Wa, const float* __restrict__ Wc) {
    __shared__ float sWa[Dd];
    int tid = threadIdx.x;
    for (int i = tid; i < Dd; i += blockDim.x) sWa[i] = Wa[i];
    __syncthreads();
    int j = blockIdx.x * blockDim.x + tid;  // 0..2D-1
    float acc = 0.f;
#pragma unroll 4
    for (int d = 0; d < Dd; d++) acc += sWa[d] * Wc[d * (2 * Dd) + j];
    g_u[j] = acc;
}

// ---------------- tiled NT GEMM: C[M,N] = A[M,K] @ Bm[N,K]^T + bias ----------------
// If FUSE_W: C = u[0:N] * (A@B^T + bias) + u[N:2N]   (the query->w fusion)
template <bool FUSE_W>
__global__ void gemm_nt_kernel(const float* __restrict__ A, const float* __restrict__ Bm,
                               const float* __restrict__ bias, float* __restrict__ C,
                               int M, int N, int K) {
    __shared__ float As[32][33];
    __shared__ float Bs[32][33];
    int tx = threadIdx.x, ty = threadIdx.y;        // 16 x 16
    int t = ty * 16 + tx;
    int row0 = blockIdx.y * 32, col0 = blockIdx.x * 32;
    float acc00 = 0.f, acc01 = 0.f, acc10 = 0.f, acc11 = 0.f;

    for (int k0 = 0; k0 < K; k0 += 32) {
#pragma unroll
        for (int i = t; i < 32 * 32; i += 256) {
            int r = i >> 5, c = i & 31;
            As[r][c] = A[(size_t)(row0 + r) * K + k0 + c];
            Bs[r][c] = Bm[(size_t)(col0 + r) * K + k0 + c];
        }
        __syncthreads();
#pragma unroll
        for (int kk = 0; kk < 32; kk++) {
            float a0 = As[ty * 2][kk], a1 = As[ty * 2 + 1][kk];
            float b0 = Bs[tx * 2][kk], b1 = Bs[tx * 2 + 1][kk];
            acc00 += a0 * b0; acc01 += a0 * b1;
            acc10 += a1 * b0; acc11 += a1 * b1;
        }
        __syncthreads();
    }

    int r0 = row0 + ty * 2, c0 = col0 + tx * 2;
    float v[2][2] = {{acc00, acc01}, {acc10, acc11}};
#pragma unroll
    for (int i = 0; i < 2; i++)
#pragma unroll
        for (int j = 0; j < 2; j++) {
            int r = r0 + i, c = c0 + j;
            float val = v[i][j] + bias[c];
            if (FUSE_W) val = g_u[c] * val + g_u[N + c];
            C[(size_t)r * N + c] = val;
        }
}

// ---------------- fused attention: logits -> softmax -> pooled ----------------
// One CTA per batch. blockDim = 768 (24 warps).
// Phase 1 streams image[b] in ascending d; phase 2 (warp-per-d) in DESCENDING d
// so the tail of phase 1 is still resident in L2.
__global__ __launch_bounds__(768, 2) void attn_kernel(const float* __restrict__ image,
                                                      const float* __restrict__ w,
                                                      float* __restrict__ pooled) {
    __shared__ float sw[Dd];
    __shared__ float sattn[Nn];
    __shared__ float sred[32];

    const int b = blockIdx.x;
    const int tid = threadIdx.x;
    const int lane = tid & 31;
    const int warp = tid >> 5;  // 0..23
    const float* img = image + (size_t)b * Dd * Nn;

    for (int i = tid; i < Dd; i += 768) sw[i] = w[b * Dd + i];
    __syncthreads();

    // ---- phase 1: logits[n] = sum_d w[d] * img[d*N + n] ----
    const int n0 = tid;             // always < 784
    const int n1 = tid + 768;       // valid only for tid < 16
    const bool has1 = (n1 < Nn);
    float l0 = 0.f, l1 = 0.f;
#pragma unroll 8
    for (int d = 0; d < Dd; d++) {
        float wd = sw[d];
        const float* rowp = img + (size_t)d * Nn;
        l0 += wd * rowp[n0];
        if (has1) l1 += wd * rowp[n1];
    }

    // ---- softmax over n (block reduce: max, then sum) ----
    float m = has1 ? fmaxf(l0, l1) : l0;
#pragma unroll
    for (int o = 16; o; o >>= 1) m = fmaxf(m, __shfl_xor_sync(0xffffffffu, m, o));
    if (lane == 0) sred[warp] = m;
    __syncthreads();
    if (warp == 0) {
        float v = (lane < 24) ? sred[lane] : -INFINITY;
#pragma unroll
        for (int o = 16; o; o >>= 1) v = fmaxf(v, __shfl_xor_sync(0xffffffffu, v, o));
        if (lane == 0) sred[0] = v;
    }
    __syncthreads();
    const float gmax = sred[0];
    __syncthreads();  // protect sred before reuse

    float e0 = expf(l0 - gmax);
    float e1 = has1 ? expf(l1 - gmax) : 0.f;
    float s = e0 + e1;
#pragma unroll
    for (int o = 16; o; o >>= 1) s += __shfl_xor_sync(0xffffffffu, s, o);
    if (lane == 0) sred[warp] = s;
    __syncthreads();
    if (warp == 0) {
        float v = (lane < 24) ? sred[lane] : 0.f;
#pragma unroll
        for (int o = 16; o; o >>= 1) v += __shfl_xor_sync(0xffffffffu, v, o);
        if (lane == 0) sred[0] = v;
    }
    __syncthreads();
    const float inv_sum = 1.f / sred[0];

    sattn[n0] = e0 * inv_sum;
    if (has1) sattn[n1] = e1 * inv_sum;
    __syncthreads();

    // ---- phase 2: pooled[d] = sum_n attn[n] * img[d*N + n], d descending ----
    for (int di = warp; di < Dd; di += 24) {
        int d = Dd - 1 - di;  // reverse order -> L2 reuse from phase 1 tail
        const float* rowp = img + (size_t)d * Nn;
        float acc = 0.f;
#pragma unroll 4
        for (int n = lane; n < Nn; n += 32) acc += sattn[n] * rowp[n];
#pragma unroll
        for (int o = 16; o; o >>= 1) acc += __shfl_xor_sync(0xffffffffu, acc, o);
        if (lane == 0) pooled[b * Dd + d] = acc;
    }
}

// ---------------- launcher ----------------
extern "C" void kernel_launch(void* const* d_in, const int* in_sizes, int n_in,
                              void* d_out, int out_size) {
    const float* in_state = (const float*)d_in[0];  // [B, S]
    const float* image    = (const float*)d_in[1];  // [B, D, N]
    const float* Wq       = (const float*)d_in[2];  // [D, S]
    const float* bq       = (const float*)d_in[3];  // [D]
    const float* Wc       = (const float*)d_in[4];  // [D, 2D]
    // d_in[5] = bc (unused: constant shift cancels in softmax)
    const float* Wa       = (const float*)d_in[6];  // [1, D]
    // d_in[7] = ba (unused: same)
    const float* Wo       = (const float*)d_in[8];  // [S, D]
    const float* bo       = (const float*)d_in[9];  // [S]
    float* out = (float*)d_out;                     // [B, S]

    float* w_ptr;      cudaGetSymbolAddress((void**)&w_ptr, g_w);
    float* pooled_ptr; cudaGetSymbolAddress((void**)&pooled_ptr, g_pooled);

    // 1) u = Wa @ Wc  (2D outputs)
    u_kernel<<<(2 * Dd) / 256, 256>>>(Wa, Wc);

    // 2) w = u1 * (in_state @ Wq^T + bq) + u2   -> g_w [B, D]
    {
        dim3 grid(Dd / 32, Bb / 32), block(16, 16);
        gemm_nt_kernel<true><<<grid, block>>>(in_state, Wq, bq, w_ptr, Bb, Dd, Ss);
    }

    // 3) fused logits -> softmax -> pooled
    attn_kernel<<<Bb, 768>>>(image, w_ptr, pooled_ptr);

    // 4) out = pooled @ Wo^T + bo
    {
        dim3 grid(Ss / 32, Bb / 32), block(16, 16);
        gemm_nt_kernel<false><<<grid, block>>>(pooled_ptr, Wo, bo, out, Bb, Ss, Dd);
    }
}

// round 2
// speedup vs baseline: 2.6544x; 2.6544x over previous
#include <cuda_runtime.h>
#include <math.h>
#include <stdint.h>

#define Bb 128
#define Ss 1024
#define Dd 512
#define Nn 784

#define TN 56                    // n-tile width (784 = 14 * 56; 56 floats = 224B = 7 sectors, aligned)
#define NTILES (Nn / TN)         // 14
#define TILE_FLOATS (Dd * TN)    // 28672
#define ATTN_THREADS 1024        // 32 warps, warp w owns d-rows [16w, 16w+16)

// ---------------- scratch (no allocations allowed) ----------------
__device__ float g_u[2 * Dd];        // Wa @ Wc : [2D]
__device__ float g_q[Bb * Dd];       // in_state @ Wq^T (no bias)
__device__ float g_pooled[Bb * Dd];  // attention-pooled features

// ---------------- cp.async helpers ----------------
__device__ __forceinline__ void cp_async16(uint32_t smem_addr, const void* gptr) {
    asm volatile("cp.async.cg.shared.global [%0], [%1], 16;\n" ::"r"(smem_addr), "l"(gptr));
}
__device__ __forceinline__ void cp_commit() { asm volatile("cp.async.commit_group;\n"); }
template <int N>
__device__ __forceinline__ void cp_wait() { asm volatile("cp.async.wait_group %0;\n" ::"n"(N)); }

// ---------------- kernel: u = Wa @ Wc (split over d, atomicAdd) ----------------
// grid (2D/256, 8); g_u must be zeroed first.
__global__ void u_kernel(const float* __restrict__ Wa, const float* __restrict__ Wc) {
    int j = blockIdx.x * 256 + threadIdx.x;  // 0..2D-1
    int d0 = blockIdx.y * 64;
    float acc = 0.f;
#pragma unroll 8
    for (int d = d0; d < d0 + 64; d++) acc += Wa[d] * Wc[(size_t)d * (2 * Dd) + j];
    atomicAdd(&g_u[j], acc);
}

// ---------------- split-K NT GEMM: C[M,N] += A[M,K] @ Bm[N,K]^T ----------------
// grid (N/32, M/32, K/kslice); 256 threads; C pre-initialized (0 or bias).
__global__ void gemm_splitk(const float* __restrict__ A, const float* __restrict__ Bm,
                            float* __restrict__ C, int M, int N, int K, int kslice) {
    __shared__ float As[32][33];
    __shared__ float Bs[32][33];
    int tx = threadIdx.x, ty = threadIdx.y;
    int t = ty * 16 + tx;
    int row0 = blockIdx.y * 32, col0 = blockIdx.x * 32;
    int kbeg = blockIdx.z * kslice;
    float acc00 = 0.f, acc01 = 0.f, acc10 = 0.f, acc11 = 0.f;

    for (int k0 = kbeg; k0 < kbeg + kslice; k0 += 32) {
#pragma unroll
        for (int i = t; i < 32 * 32; i += 256) {
            int r = i >> 5, c = i & 31;
            As[r][c] = A[(size_t)(row0 + r) * K + k0 + c];
            Bs[r][c] = Bm[(size_t)(col0 + r) * K + k0 + c];
        }
        __syncthreads();
#pragma unroll
        for (int kk = 0; kk < 32; kk++) {
            float a0 = As[ty * 2][kk], a1 = As[ty * 2 + 1][kk];
            float b0 = Bs[tx * 2][kk], b1 = Bs[tx * 2 + 1][kk];
            acc00 += a0 * b0; acc01 += a0 * b1;
            acc10 += a1 * b0; acc11 += a1 * b1;
        }
        __syncthreads();
    }
    int r0 = row0 + ty * 2, c0 = col0 + tx * 2;
    atomicAdd(&C[(size_t)r0 * N + c0], acc00);
    atomicAdd(&C[(size_t)r0 * N + c0 + 1], acc01);
    atomicAdd(&C[(size_t)(r0 + 1) * N + c0], acc10);
    atomicAdd(&C[(size_t)(r0 + 1) * N + c0 + 1], acc11);
}

// ---------------- bias init: out[b,s] = bo[s] ----------------
__global__ void bias_init_kernel(float* __restrict__ out, const float* __restrict__ bo) {
    int i = blockIdx.x * 1024 + threadIdx.x;  // M*N = 131072
    out[i] = bo[i & (Ss - 1)];
}

// ---------------- single-pass flash attention over spatial dim ----------------
// One CTA per batch. Reads image[b] exactly once (14 double-buffered tiles).
// sw[d] = u1[d]*(q[b,d]+bq[d]) + u2[d]; logits[n] = sum_d sw[d]*img[d,n];
// online softmax; pooled[d] = sum_n attn[n]*img[d,n].
__global__ __launch_bounds__(ATTN_THREADS, 1) void attn_flash(
    const float* __restrict__ image, const float* __restrict__ bq) {
    extern __shared__ float smem[];
    float* bufs = smem;                         // 2 * TILE_FLOATS
    float* slog = smem + 2 * TILE_FLOATS;       // 64
    float* sp   = slog + 64;                    // 64
    float* sctl = sp + 64;                      // [0]=scale, [1]=Z

    const int b = blockIdx.x;
    const int tid = threadIdx.x;
    const int lane = tid & 31;
    const int warp = tid >> 5;                  // 0..31
    const float* imgb = image + (size_t)b * Dd * Nn;
    const uint32_t smem_base = (uint32_t)__cvta_generic_to_shared(bufs);

    // per-warp sw values: lane l (<16) holds sw[warp*16 + l]
    float swv = 0.f;
    if (lane < 16) {
        int d = warp * 16 + lane;
        float qv = g_q[b * Dd + d] + bq[d];
        swv = g_u[d] * qv + g_u[Dd + d];
    }

    if (tid < 56) slog[tid] = 0.f;

    float acc[16];
#pragma unroll
    for (int i = 0; i < 16; i++) acc[i] = 0.f;
    float m = -INFINITY, Zl = 0.f;

    // prologue: tile 0 -> buf 0
    {
        const char* gbase = (const char*)imgb;
        for (int f = tid; f < TILE_FLOATS / 4; f += ATTN_THREADS) {
            int row = f / (TN / 4);
            int seg = f % (TN / 4);
            cp_async16(smem_base + (uint32_t)(row * TN + seg * 4) * 4,
                       gbase + ((size_t)row * Nn + seg * 4) * 4);
        }
        cp_commit();
    }

    for (int t = 0; t < NTILES; t++) {
        const float* cur = bufs + (t & 1) * TILE_FLOATS;

        // prefetch tile t+1 into other buffer
        if (t + 1 < NTILES) {
            uint32_t dst = smem_base + (uint32_t)(((t + 1) & 1) * TILE_FLOATS) * 4;
            const char* gbase = (const char*)(imgb + (t + 1) * TN);
            for (int f = tid; f < TILE_FLOATS / 4; f += ATTN_THREADS) {
                int row = f / (TN / 4);
                int seg = f % (TN / 4);
                cp_async16(dst + (uint32_t)(row * TN + seg * 4) * 4,
                           gbase + ((size_t)row * Nn + seg * 4) * 4);
            }
            cp_commit();
            cp_wait<1>();
        } else {
            cp_wait<0>();
        }
        __syncthreads();  // tile t ready; slog zeroed

        // ---- tile logits: warp w covers d in [16w, 16w+16) ----
        const float* wrows = cur + warp * 16 * TN;
        float a0 = 0.f, a1 = 0.f;
#pragma unroll
        for (int i = 0; i < 16; i++) {
            float wd = __shfl_sync(0xffffffffu, swv, i);
            a0 += wd * wrows[i * TN + lane];
            if (lane < 24) a1 += wd * wrows[i * TN + 32 + lane];
        }
        atomicAdd(&slog[lane], a0);
        if (lane < 24) atomicAdd(&slog[32 + lane], a1);
        __syncthreads();

        // ---- online softmax update (warp 0) ----
        if (warp == 0) {
            float v0 = slog[lane];
            float v1 = (lane < 24) ? slog[32 + lane] : -INFINITY;
            float tmax = fmaxf(v0, v1);
#pragma unroll
            for (int o = 16; o; o >>= 1) tmax = fmaxf(tmax, __shfl_xor_sync(0xffffffffu, tmax, o));
            float newm = fmaxf(m, tmax);
            float e0 = __expf(v0 - newm);
            float e1 = (lane < 24) ? __expf(v1 - newm) : 0.f;
            sp[lane] = e0;
            if (lane < 24) sp[32 + lane] = e1;
            float ts = e0 + e1;
#pragma unroll
            for (int o = 16; o; o >>= 1) ts += __shfl_xor_sync(0xffffffffu, ts, o);
            float sc = __expf(m - newm);
            Zl = Zl * sc + ts;
            m = newm;
            if (lane == 0) sctl[0] = sc;
            // re-zero slog for next tile
            slog[lane] = 0.f;
            if (lane < 24) slog[32 + lane] = 0.f;
        }
        __syncthreads();

        // ---- pooled accumulate (lane-distributed, rescale-on-the-fly) ----
        float sc = sctl[0];
        float p0 = sp[lane];
        float p1 = (lane < 24) ? sp[32 + lane] : 0.f;
#pragma unroll
        for (int i = 0; i < 16; i++) {
            float v = acc[i] * sc;
            v += p0 * wrows[i * TN + lane];
            if (lane < 24) v += p1 * wrows[i * TN + 32 + lane];
            acc[i] = v;
        }
        __syncthreads();  // all reads of cur done before next prefetch overwrites it
    }

    if (warp == 0 && lane == 0) sctl[1] = Zl;
    __syncthreads();
    const float invZ = 1.f / sctl[1];

#pragma unroll
    for (int i = 0; i < 16; i++) {
        float v = acc[i];
#pragma unroll
        for (int o = 16; o; o >>= 1) v += __shfl_xor_sync(0xffffffffu, v, o);
        if (lane == 0) g_pooled[b * Dd + warp * 16 + i] = v * invZ;
    }
}

// ---------------- launcher ----------------
extern "C" void kernel_launch(void* const* d_in, const int* in_sizes, int n_in,
                              void* d_out, int out_size) {
    const float* in_state = (const float*)d_in[0];  // [B, S]
    const float* image    = (const float*)d_in[1];  // [B, D, N]
    const float* Wq       = (const float*)d_in[2];  // [D, S]
    const float* bq       = (const float*)d_in[3];  // [D]
    const float* Wc       = (const float*)d_in[4];  // [D, 2D]
    // d_in[5] = bc (cancels in softmax)
    const float* Wa       = (const float*)d_in[6];  // [1, D]
    // d_in[7] = ba (cancels in softmax)
    const float* Wo       = (const float*)d_in[8];  // [S, D]
    const float* bo       = (const float*)d_in[9];  // [S]
    float* out = (float*)d_out;                     // [B, S]

    float* u_ptr;      cudaGetSymbolAddress((void**)&u_ptr, g_u);
    float* q_ptr;      cudaGetSymbolAddress((void**)&q_ptr, g_q);
    float* pooled_ptr; cudaGetSymbolAddress((void**)&pooled_ptr, g_pooled);

    static bool attr_set = false;
    if (!attr_set) {
        cudaFuncSetAttribute(attn_flash, cudaFuncAttributeMaxDynamicSharedMemorySize,
                             (2 * TILE_FLOATS + 64 + 64 + 8) * sizeof(float));
        attr_set = true;
    }

    // zero accumulators
    cudaMemsetAsync(u_ptr, 0, 2 * Dd * sizeof(float));
    cudaMemsetAsync(q_ptr, 0, Bb * Dd * sizeof(float));

    // 1) u = Wa @ Wc (split over d)
    {
        dim3 grid(2 * Dd / 256, 8);
        u_kernel<<<grid, 256>>>(Wa, Wc);
    }

    // 2) q = in_state @ Wq^T (split-K x4)
    {
        dim3 grid(Dd / 32, Bb / 32, 4), block(16, 16);
        gemm_splitk<<<grid, block>>>(in_state, Wq, q_ptr, Bb, Dd, Ss, Ss / 4);
    }

    // 3) single-pass attention: logits -> online softmax -> pooled
    {
        size_t smem_bytes = (2 * TILE_FLOATS + 64 + 64 + 8) * sizeof(float);
        attn_flash<<<Bb, ATTN_THREADS, smem_bytes>>>(image, bq);
    }

    // 4) out = bo, then out += pooled @ Wo^T (split-K x4)
    bias_init_kernel<<<Bb * Ss / 1024, 1024>>>(out, bo);
    {
        dim3 grid(Ss / 32, Bb / 32, 4), block(16, 16);
        gemm_splitk<<<grid, block>>>(pooled_ptr, Wo, out, Bb, Ss, Dd, Dd / 4);
    }
}